// round 6
// baseline (speedup 1.0000x reference)
#include <cuda_runtime.h>
#include <cstdint>

// ============================ problem constants ============================
constexpr int IMGC = 224;
constexpr int KTOT = IMGC * IMGC;     // 50176
constexpr int BQ   = 256;
constexpr int JN   = 25;
constexpr int TN   = 64;
constexpr int OUTN = 256;
constexpr int MIDJ = JN / 2;          // 12
constexpr int BOXC = 20;

constexpr int XG   = 56;              // x groups
constexpr int XPG  = 4;               // x per group
constexpr int SROW = 128;             // floats per S row (n-half per CTA)
constexpr int SBUF = IMGC * SROW;     // 28672 floats per buffer
constexpr uint32_t SMEM_MAIN = 2u * SBUF * 4;   // 229376 B (double-buffered S)

// ============================ scratch (device globals) =====================
__device__ __align__(256) unsigned long long g_bits[(size_t)IMGC * BQ * 4]; // 1.8MB
__device__ __align__(256) float g_part[(size_t)XG * BQ * OUTN];             // 14.7MB
__device__ int g_px[BQ * JN];
__device__ int g_ylo[BQ * JN];
__device__ int g_yhi[BQ * JN];

// ============================ kernel 1: farthest-frame box params ==========
__global__ void prep_kernel(const float* __restrict__ sk) {
    int id = blockIdx.x * blockDim.x + threadIdx.x;
    if (id >= BQ * JN) return;
    int b = id / JN, j = id % JN;
    const float* base = sk + ((size_t)b * JN + j) * TN * 3;
    const float* midb = sk + ((size_t)b * JN + MIDJ) * TN * 3;

    float best = -1.0f;
    int   tb = 0;
    for (int t = 0; t < TN; t++) {
        float dx = base[t * 3 + 0] - midb[t * 3 + 0];
        float dy = base[t * 3 + 1] - midb[t * 3 + 1];
        float dz = base[t * 3 + 2] - midb[t * 3 + 2];
        float d2 = __fadd_rn(__fadd_rn(__fmul_rn(dx, dx), __fmul_rn(dy, dy)),
                             __fmul_rn(dz, dz));
        float d = __fsqrt_rn(d2);
        if (d > best) { best = d; tb = t; }   // first-max == argmax semantics
    }
    float x = base[tb * 3 + 0];
    float y = base[tb * 3 + 1];
    int px = (int)(__fmul_rn(x, 224.0f));     // truncation == astype(int32)
    int py = (int)(__fmul_rn(y, 224.0f));
    g_px[id]  = px;
    g_ylo[id] = (py < BOXC) ? 0 : py - BOXC;
    g_yhi[id] = (py > IMGC - BOXC) ? IMGC : py + BOXC;
}

// ============================ kernel 2: per-(b,x) y-bitmask =================
__global__ void bitmask_kernel() {
    const int x = blockIdx.x;
    const int b = threadIdx.x;

    unsigned long long m[4] = {0ull, 0ull, 0ull, 0ull};
#pragma unroll
    for (int j = 0; j < JN; j++) {
        if (j == MIDJ) continue;
        int px = g_px[b * JN + j];
        if (x >= px - BOXC && x < px + BOXC) {
            int lo = g_ylo[b * JN + j];
            int hi = g_yhi[b * JN + j];
#pragma unroll
            for (int w = 0; w < 4; w++) {
                int l = lo - w * 64;  if (l < 0)  l = 0;
                int h = hi - w * 64;  if (h > 64) h = 64;
                if (l < h) {
                    unsigned long long hiM = (h == 64) ? ~0ull : ((1ull << h) - 1ull);
                    unsigned long long loM = (1ull << l) - 1ull;
                    m[w] |= hiM & ~loM;
                }
            }
        }
    }
    unsigned long long* dst = g_bits + ((size_t)x * BQ + b) * 4;
    dst[0] = m[0]; dst[1] = m[1]; dst[2] = m[2]; dst[3] = m[3];
}

// ============================ kernel 3: warp-specialized scan+gather ========
// grid (XG, 2): xg, n-half. 512 threads = 16 warps:
//   warps 0-3  : producers — y-prefix-scan of W columns for x+1 into S buf
//   warps 4-15 : consumers — per-batch uniform bitmask walk gathering S rows
// S layout: S[y][n_phys] with n_phys = n ^ (y & 31)  (conflict-free both ways,
// and +32c n-offsets stay LDS immediates since (lane^r)+32c == (lane+32c)^r).
// Sign trick: D = m ^ (m>>1) marks transitions; signs alternate starting at
// +1 iff bit0 of m is set.
__global__ __launch_bounds__(512, 1)
void main_kernel(const float* __restrict__ W) {
    extern __shared__ float sS[];
    const int tid  = threadIdx.x;
    const int w    = tid >> 5;
    const int lane = tid & 31;
    const int xg   = blockIdx.x;
    const int n0   = blockIdx.y * 128;

    float4 acc[22];
#pragma unroll
    for (int k = 0; k < 22; k++) acc[k] = make_float4(0.f, 0.f, 0.f, 0.f);
    const int gw = w - 4;   // gather warp id 0..11; b = gw + 12*k (balanced)

    for (int ph = 0; ph <= XPG; ph++) {
        // ---------------- producers: scan x = xg*XPG + ph -------------------
        if (w < 4 && ph < XPG) {
            const int x = xg * XPG + ph;
            float* S = sS + (ph & 1) * SBUF;
            const float* pw = W + (size_t)(n0 + w * 32) * KTOT + x * IMGC + lane;

            float v[7];
#pragma unroll
            for (int s = 0; s < 7; s++) v[s] = __ldg(pw + s * 32);

#pragma unroll 1
            for (int nn = 0; nn < 32; nn++) {
                // prefetch next column while scanning current
                float vn[7];
                const int nnx = (nn + 1 < 32) ? nn + 1 : nn;
                const float* pn = pw + (size_t)nnx * KTOT;
#pragma unroll
                for (int s = 0; s < 7; s++) vn[s] = __ldg(pn + s * 32);

                const int n = w * 32 + nn;
                float carry = 0.f;
#pragma unroll
                for (int s = 0; s < 7; s++) {
                    float val = v[s];
#pragma unroll
                    for (int off = 1; off < 32; off <<= 1) {
                        float t = __shfl_up_sync(0xffffffffu, val, off);
                        if (lane >= off) val += t;
                    }
                    val += carry;
                    const int y = s * 32 + lane;
                    S[y * SROW + (n ^ (y & 31))] = val;
                    carry = __shfl_sync(0xffffffffu, val, 31);
                }
#pragma unroll
                for (int s = 0; s < 7; s++) v[s] = vn[s];
            }
        }
        // ---------------- consumers: gather x = xg*XPG + ph - 1 -------------
        if (w >= 4 && ph >= 1) {
            const int x = xg * XPG + ph - 1;
            const float* S = sS + ((ph - 1) & 1) * SBUF;
#pragma unroll
            for (int k = 0; k < 22; k++) {
                const int b = gw + 12 * k;
                if (b < BQ) {
                    const ulonglong2* mp = reinterpret_cast<const ulonglong2*>(
                        g_bits + ((size_t)x * BQ + b) * 4);
                    ulonglong2 mA = __ldg(mp), mB = __ldg(mp + 1);
                    unsigned long long D0 = mA.x ^ ((mA.x >> 1) | (mA.y << 63));
                    unsigned long long D1 = mA.y ^ ((mA.y >> 1) | (mB.x << 63));
                    unsigned long long D2 = mB.x ^ ((mB.x >> 1) | (mB.y << 63));
                    unsigned long long D3 = mB.y ^ (mB.y >> 1);
                    float sgn = (mA.x & 1ull) ? 1.f : -1.f;
                    unsigned long long D[4] = {D0, D1, D2, D3};
#pragma unroll
                    for (int wd = 0; wd < 4; wd++) {
                        unsigned long long d = D[wd];
                        while (d) {
                            int p = __ffsll((long long)d) - 1;
                            d &= d - 1;
                            const int y = wd * 64 + p;
                            const float* row = S + y * SROW + (lane ^ (y & 31));
                            float t0 = row[0];
                            float t1 = row[32];
                            float t2 = row[64];
                            float t3 = row[96];
                            acc[k].x = fmaf(sgn, t0, acc[k].x);
                            acc[k].y = fmaf(sgn, t1, acc[k].y);
                            acc[k].z = fmaf(sgn, t2, acc[k].z);
                            acc[k].w = fmaf(sgn, t3, acc[k].w);
                            sgn = -sgn;
                        }
                    }
                }
            }
        }
        __syncthreads();
    }

    // ---------------- write partials ----------------------------------------
    if (w >= 4) {
#pragma unroll
        for (int k = 0; k < 22; k++) {
            const int b = gw + 12 * k;
            if (b < BQ) {
                float* dst = g_part + ((size_t)xg * BQ + b) * OUTN + n0 + lane;
                dst[0]  = acc[k].x;
                dst[32] = acc[k].y;
                dst[64] = acc[k].z;
                dst[96] = acc[k].w;
            }
        }
    }
}

// ============================ kernel 4: reduce + bias + rgb multiply ========
__global__ void final_kernel(const float* __restrict__ rgb,
                             const float* __restrict__ bias,
                             float* __restrict__ out) {
    const int b = blockIdx.x;
    const int o = threadIdx.x;
    float acc = 0.0f;
    const float* p = g_part + b * OUTN + o;
#pragma unroll 8
    for (int s = 0; s < XG; s++)
        acc += p[(size_t)s * (BQ * OUTN)];
    out[b * OUTN + o] = rgb[b * OUTN + o] * (acc + bias[o]);
}

// ============================ launch ========================================
extern "C" void kernel_launch(void* const* d_in, const int* in_sizes, int n_in,
                              void* d_out, int out_size) {
    const float* rgb = nullptr;
    const float* sk  = nullptr;
    const float* W   = nullptr;
    const float* bias = nullptr;
    for (int i = 0; i < n_in; i++) {
        switch (in_sizes[i]) {
            case BQ * OUTN:          rgb  = (const float*)d_in[i]; break;
            case BQ * JN * TN * 3:   sk   = (const float*)d_in[i]; break;
            case OUTN * KTOT:        W    = (const float*)d_in[i]; break;
            case OUTN:               bias = (const float*)d_in[i]; break;
            default: break;
        }
    }
    float* out = (float*)d_out;

    cudaFuncSetAttribute(main_kernel,
                         cudaFuncAttributeMaxDynamicSharedMemorySize, SMEM_MAIN);

    prep_kernel<<<(BQ * JN + 255) / 256, 256>>>(sk);
    bitmask_kernel<<<IMGC, BQ>>>();
    main_kernel<<<dim3(XG, 2), 512, SMEM_MAIN>>>(W);
    final_kernel<<<BQ, OUTN>>>(rgb, bias, out);
}